// round 1
// baseline (speedup 1.0000x reference)
#include <cuda_runtime.h>
#include <math.h>

// Problem constants
constexpr int Bb = 2;
constexpr int Ts = 2048;
constexpr int Dm = 1024;
constexpr int Hh = 16;
constexpr int Dh = 64;          // head dim
constexpr int BT = Bb * Ts;     // 4096 rows

// Scratch (device globals — no allocation allowed)
__device__ float g_qkv[BT * 3 * Dm];          // [BT, 3*Dm]
__device__ float g_q[Bb * Hh * Ts * Dh];      // [b,h,t,d] after RoPE
__device__ float g_k[Bb * Hh * Ts * Dh];
__device__ float g_v[Bb * Hh * Ts * Dh];
__device__ float g_attn[BT * Dm];             // [BT, Dm] attention output

// ---------------------------------------------------------------------------
// Tiled fp32 GEMM with bias: C[M,N] = A[M,K] @ B[K,N] + bias[N]
// Tiles: 64x64x16, 256 threads, each thread computes 4x4.
// Requires M%64==0, N%64==0, K%16==0 (true for all our shapes).
// ---------------------------------------------------------------------------
constexpr int TM = 64, TN = 64, TK = 16;

__global__ __launch_bounds__(256) void gemm_bias_kernel(
    const float* __restrict__ A, const float* __restrict__ Bm,
    const float* __restrict__ bias, float* __restrict__ C,
    int M, int N, int K)
{
    __shared__ float As[TK][TM + 4];   // transposed A tile: As[k][m]
    __shared__ float Bs[TK][TN + 4];

    const int tid = threadIdx.x;
    const int tx = tid & 15;        // 0..15 (cols)
    const int ty = tid >> 4;        // 0..15 (rows)
    const int row0 = blockIdx.y * TM;
    const int col0 = blockIdx.x * TN;

    float acc[4][4] = {};

    for (int k0 = 0; k0 < K; k0 += TK) {
        // Load A tile: 64 rows x 16 cols; each thread one float4.
        {
            int r = tid >> 2;              // 0..63
            int c = (tid & 3) * 4;         // 0,4,8,12
            float4 v = *reinterpret_cast<const float4*>(
                &A[(size_t)(row0 + r) * K + k0 + c]);
            As[c + 0][r] = v.x;
            As[c + 1][r] = v.y;
            As[c + 2][r] = v.z;
            As[c + 3][r] = v.w;
        }
        // Load B tile: 16 rows x 64 cols; each thread one float4.
        {
            int r = tid >> 4;              // 0..15
            int c = (tid & 15) * 4;        // 0..60
            float4 v = *reinterpret_cast<const float4*>(
                &Bm[(size_t)(k0 + r) * N + col0 + c]);
            *reinterpret_cast<float4*>(&Bs[r][c]) = v;
        }
        __syncthreads();

        #pragma unroll
        for (int kk = 0; kk < TK; kk++) {
            float a[4], b[4];
            #pragma unroll
            for (int i = 0; i < 4; i++) a[i] = As[kk][ty * 4 + i];
            #pragma unroll
            for (int j = 0; j < 4; j++) b[j] = Bs[kk][tx * 4 + j];
            #pragma unroll
            for (int i = 0; i < 4; i++)
                #pragma unroll
                for (int j = 0; j < 4; j++)
                    acc[i][j] += a[i] * b[j];
        }
        __syncthreads();
    }

    #pragma unroll
    for (int i = 0; i < 4; i++) {
        int r = row0 + ty * 4 + i;
        #pragma unroll
        for (int j = 0; j < 4; j++) {
            int c = col0 + tx * 4 + j;
            C[(size_t)r * N + c] = acc[i][j] + bias[c];
        }
    }
}

// ---------------------------------------------------------------------------
// RoPE + scatter: read g_qkv [BT, 3*Dm], write g_q/g_k (rotated) and g_v
// in [b,h,t,d] layout. One thread per (b,t,h,pair).
// ---------------------------------------------------------------------------
__global__ void rope_scatter_kernel()
{
    int idx = blockIdx.x * blockDim.x + threadIdx.x;
    const int NPAIR = Dh / 2;
    const int TOTAL = Bb * Ts * Hh * NPAIR;
    if (idx >= TOTAL) return;

    int p = idx % NPAIR;
    int h = (idx / NPAIR) % Hh;
    int t = (idx / (NPAIR * Hh)) % Ts;
    int b = idx / (NPAIR * Hh * Ts);

    const float* row = g_qkv + (size_t)(b * Ts + t) * (3 * Dm);
    int col = h * Dh + 2 * p;

    // inv_freq = 10000^(-(2p)/Dh)
    float e = -((float)(2 * p) / (float)Dh) * log2f(10000.0f);
    float inv_freq = exp2f(e);
    float ang = (float)t * inv_freq;
    float s, c;
    sincosf(ang, &s, &c);

    float qe = row[col],         qo = row[col + 1];
    float ke = row[Dm + col],    ko = row[Dm + col + 1];
    float ve = row[2 * Dm + col], vo = row[2 * Dm + col + 1];

    size_t base = ((size_t)(b * Hh + h) * Ts + t) * Dh + 2 * p;
    g_q[base]     = qe * c - qo * s;
    g_q[base + 1] = qe * s + qo * c;
    g_k[base]     = ke * c - ko * s;
    g_k[base + 1] = ke * s + ko * c;
    g_v[base]     = ve;
    g_v[base + 1] = vo;
}

// ---------------------------------------------------------------------------
// Flash attention (fp32, causal + pad mask). One thread = one query row.
// Block: 128 threads = 128 query rows of one (b,h). K/V tiles of 64 in smem.
// ---------------------------------------------------------------------------
constexpr int QROWS = 128;
constexpr int KTILE = 64;

__global__ __launch_bounds__(QROWS) void flash_attn_kernel(
    const int* __restrict__ amask)
{
    __shared__ float Ks[KTILE][Dh];
    __shared__ float Vs[KTILE][Dh];
    __shared__ int   Ms[KTILE];

    const int tid = threadIdx.x;
    const int h = blockIdx.y;
    const int b = blockIdx.z;
    const int t = blockIdx.x * QROWS + tid;

    const float* qptr = g_q + ((size_t)(b * Hh + h) * Ts + t) * Dh;
    float q[Dh], o[Dh];
    #pragma unroll
    for (int d = 0; d < Dh; d++) { q[d] = qptr[d]; o[d] = 0.0f; }

    float m = -1e30f, l = 0.0f;
    const float scale = 0.125f;   // 1/sqrt(64)
    const int tend = blockIdx.x * QROWS + QROWS - 1;

    const float* kbase0 = g_k + ((size_t)(b * Hh + h) * Ts) * Dh;
    const float* vbase0 = g_v + ((size_t)(b * Hh + h) * Ts) * Dh;

    for (int k0 = 0; k0 <= tend; k0 += KTILE) {
        // cooperative tile load: 64x64 floats each = 1024 float4, 128 thr -> 8 each
        const float* kbase = kbase0 + (size_t)k0 * Dh;
        const float* vbase = vbase0 + (size_t)k0 * Dh;
        #pragma unroll
        for (int i = 0; i < 8; i++) {
            int e = i * QROWS + tid;       // float4 index 0..1023
            int r = e >> 4;                // 16 float4 per row
            int c = (e & 15) * 4;
            *reinterpret_cast<float4*>(&Ks[r][c]) =
                *reinterpret_cast<const float4*>(&kbase[(size_t)r * Dh + c]);
            *reinterpret_cast<float4*>(&Vs[r][c]) =
                *reinterpret_cast<const float4*>(&vbase[(size_t)r * Dh + c]);
        }
        if (tid < KTILE) Ms[tid] = amask[b * Ts + k0 + tid];
        __syncthreads();

        int jmax = t - k0 + 1;                 // causal: key index <= t
        if (jmax > KTILE) jmax = KTILE;
        for (int j = 0; j < jmax; j++) {
            if (!Ms[j]) continue;              // pad mask
            float s = 0.0f;
            #pragma unroll
            for (int d = 0; d < Dh; d++) s += q[d] * Ks[j][d];
            s *= scale;
            if (s > m) {
                float corr = __expf(m - s);
                m = s;
                l *= corr;
                #pragma unroll
                for (int d = 0; d < Dh; d++) o[d] *= corr;
            }
            float p = __expf(s - m);
            l += p;
            #pragma unroll
            for (int d = 0; d < Dh; d++) o[d] += p * Vs[j][d];
        }
        __syncthreads();
    }

    float inv_l = (l > 0.0f) ? (1.0f / l) : 0.0f;
    float* outp = g_attn + (size_t)(b * Ts + t) * Dm + h * Dh;
    #pragma unroll
    for (int d = 0; d < Dh; d++) outp[d] = o[d] * inv_l;
}

// ---------------------------------------------------------------------------
// Launch
// ---------------------------------------------------------------------------
extern "C" void kernel_launch(void* const* d_in, const int* in_sizes, int n_in,
                              void* d_out, int out_size)
{
    const float* x      = (const float*)d_in[0];
    const int*   amask  = (const int*)  d_in[1];
    const float* W_qkv  = (const float*)d_in[2];
    const float* b_qkv  = (const float*)d_in[3];
    const float* W_out  = (const float*)d_in[4];
    const float* b_out  = (const float*)d_in[5];
    float* out = (float*)d_out;

    float *p_qkv, *p_attn;
    cudaGetSymbolAddress((void**)&p_qkv,  g_qkv);
    cudaGetSymbolAddress((void**)&p_attn, g_attn);

    // 1) QKV GEMM: [4096,1024] @ [1024,3072] + bias
    {
        dim3 grid((3 * Dm) / TN, BT / TM);
        gemm_bias_kernel<<<grid, 256>>>(x, W_qkv, b_qkv, p_qkv, BT, 3 * Dm, Dm);
    }
    // 2) RoPE + scatter to [b,h,t,d]
    {
        int total = Bb * Ts * Hh * (Dh / 2);
        rope_scatter_kernel<<<(total + 255) / 256, 256>>>();
    }
    // 3) Flash attention
    {
        dim3 grid(Ts / QROWS, Hh, Bb);
        flash_attn_kernel<<<grid, QROWS>>>(amask);
    }
    // 4) Output projection: [4096,1024] @ [1024,1024] + bias -> d_out
    {
        dim3 grid(Dm / TN, BT / TM);
        gemm_bias_kernel<<<grid, 256>>>(p_attn, W_out, b_out, out, BT, Dm, Dm);
    }
}

// round 3
// speedup vs baseline: 3.0874x; 3.0874x over previous
#include <cuda_runtime.h>
#include <math.h>
#include <stdint.h>

// Problem constants
constexpr int Bb = 2;
constexpr int Ts = 2048;
constexpr int Dm = 1024;
constexpr int Hh = 16;
constexpr int Dh = 64;          // head dim
constexpr int BT = Bb * Ts;     // 4096 rows

// Scratch (device globals — no allocation allowed)
__device__ float g_qkv[BT * 3 * Dm];          // [BT, 3*Dm]
__device__ float g_q[Bb * Hh * Ts * Dh];      // [b,h,t,d] after RoPE
__device__ float g_k[Bb * Hh * Ts * Dh];
__device__ float g_v[Bb * Hh * Ts * Dh];
__device__ float g_attn[BT * Dm];             // [BT, Dm] attention output

// ---------------------------------------------------------------------------
// tf32 helpers
// ---------------------------------------------------------------------------
__device__ __forceinline__ uint32_t f2tf32(float f) {
    uint32_t r;
    asm("cvt.rna.tf32.f32 %0, %1;" : "=r"(r) : "f"(f));
    return r;
}

__device__ __forceinline__ void mma_tf32(float* c, const uint32_t* a, const uint32_t* b) {
    asm volatile(
        "mma.sync.aligned.m16n8k8.row.col.f32.tf32.tf32.f32 "
        "{%0,%1,%2,%3},{%4,%5,%6,%7},{%8,%9},{%0,%1,%2,%3};"
        : "+f"(c[0]), "+f"(c[1]), "+f"(c[2]), "+f"(c[3])
        : "r"(a[0]), "r"(a[1]), "r"(a[2]), "r"(a[3]), "r"(b[0]), "r"(b[1]));
}

// ---------------------------------------------------------------------------
// TF32 tensor-core GEMM with bias: C[M,N] = A[M,K] @ B[K,N] + bias[N]
// Block tile 128x128x32, 256 threads (8 warps), warp tile 64x32.
// tf32 conversion happens at smem store; mainloop is pure LDS + MMA.
// ---------------------------------------------------------------------------
constexpr int GBM = 128, GBN = 128, GBK = 32;

__global__ __launch_bounds__(256) void gemm_tf32_kernel(
    const float* __restrict__ A, const float* __restrict__ Bm,
    const float* __restrict__ bias, float* __restrict__ C,
    int M, int N, int K)
{
    __shared__ uint32_t As[GBK][GBM + 4];   // As[k][m], tf32 bit patterns
    __shared__ uint32_t Bs[GBK][GBN + 4];   // Bs[k][n]

    const int tid = threadIdx.x;
    const int wid = tid >> 5;
    const int lane = tid & 31;
    const int lr = lane >> 2;    // 0..7
    const int lc = lane & 3;     // 0..3
    const int wm = (wid >> 2) * 64;   // warp row offset (0 or 64)
    const int wn = (wid & 3) * 32;    // warp col offset
    const int row0 = blockIdx.y * GBM;
    const int col0 = blockIdx.x * GBN;

    float acc[4][4][4] = {};   // [mf][nf][4]

    for (int k0 = 0; k0 < K; k0 += GBK) {
        // Load A 128x32 -> transposed As[k][m], converting to tf32.
        #pragma unroll
        for (int i = 0; i < 4; i++) {
            int e = i * 256 + tid;         // float4 index 0..1023
            int r = e >> 3;                // 0..127
            int c = (e & 7) * 4;           // 0..28
            float4 v = *reinterpret_cast<const float4*>(
                &A[(size_t)(row0 + r) * K + k0 + c]);
            As[c + 0][r] = f2tf32(v.x);
            As[c + 1][r] = f2tf32(v.y);
            As[c + 2][r] = f2tf32(v.z);
            As[c + 3][r] = f2tf32(v.w);
        }
        // Load B 32x128 -> Bs[k][n], converting to tf32.
        #pragma unroll
        for (int i = 0; i < 4; i++) {
            int e = i * 256 + tid;
            int r = e >> 5;                // 0..31
            int c = (e & 31) * 4;          // 0..124
            float4 v = *reinterpret_cast<const float4*>(
                &Bm[(size_t)(k0 + r) * N + col0 + c]);
            Bs[r][c]     = f2tf32(v.x);
            Bs[r][c + 1] = f2tf32(v.y);
            Bs[r][c + 2] = f2tf32(v.z);
            Bs[r][c + 3] = f2tf32(v.w);
        }
        __syncthreads();

        #pragma unroll
        for (int kk = 0; kk < GBK; kk += 8) {
            uint32_t af[4][4];
            uint32_t bf[4][2];
            #pragma unroll
            for (int mf = 0; mf < 4; mf++) {
                int mb = wm + mf * 16;
                af[mf][0] = As[kk + lc][mb + lr];
                af[mf][1] = As[kk + lc][mb + lr + 8];
                af[mf][2] = As[kk + lc + 4][mb + lr];
                af[mf][3] = As[kk + lc + 4][mb + lr + 8];
            }
            #pragma unroll
            for (int nf = 0; nf < 4; nf++) {
                int nb = wn + nf * 8;
                bf[nf][0] = Bs[kk + lc][nb + lr];
                bf[nf][1] = Bs[kk + lc + 4][nb + lr];
            }
            #pragma unroll
            for (int mf = 0; mf < 4; mf++)
                #pragma unroll
                for (int nf = 0; nf < 4; nf++)
                    mma_tf32(acc[mf][nf], af[mf], bf[nf]);
        }
        __syncthreads();
    }

    // Epilogue. C fragment layout: c0:(r,2c) c1:(r,2c+1) c2:(r+8,2c) c3:(r+8,2c+1)
    #pragma unroll
    for (int mf = 0; mf < 4; mf++) {
        int r = row0 + wm + mf * 16 + lr;
        #pragma unroll
        for (int nf = 0; nf < 4; nf++) {
            int c = col0 + wn + nf * 8 + 2 * lc;
            C[(size_t)r * N + c]           = acc[mf][nf][0] + bias[c];
            C[(size_t)r * N + c + 1]       = acc[mf][nf][1] + bias[c + 1];
            C[(size_t)(r + 8) * N + c]     = acc[mf][nf][2] + bias[c];
            C[(size_t)(r + 8) * N + c + 1] = acc[mf][nf][3] + bias[c + 1];
        }
    }
}

// ---------------------------------------------------------------------------
// RoPE + scatter: read g_qkv [BT, 3*Dm], write g_q/g_k (rotated) and g_v
// in [b,h,t,d] layout. One thread per (b,t,h,pair).
// ---------------------------------------------------------------------------
__global__ void rope_scatter_kernel()
{
    int idx = blockIdx.x * blockDim.x + threadIdx.x;
    const int NPAIR = Dh / 2;
    const int TOTAL = Bb * Ts * Hh * NPAIR;
    if (idx >= TOTAL) return;

    int p = idx % NPAIR;
    int h = (idx / NPAIR) % Hh;
    int t = (idx / (NPAIR * Hh)) % Ts;
    int b = idx / (NPAIR * Hh * Ts);

    const float* row = g_qkv + (size_t)(b * Ts + t) * (3 * Dm);
    int col = h * Dh + 2 * p;

    float e = -((float)(2 * p) / (float)Dh) * log2f(10000.0f);
    float inv_freq = exp2f(e);
    float ang = (float)t * inv_freq;
    float s, c;
    sincosf(ang, &s, &c);

    float qe = row[col],          qo = row[col + 1];
    float ke = row[Dm + col],     ko = row[Dm + col + 1];
    float ve = row[2 * Dm + col], vo = row[2 * Dm + col + 1];

    size_t base = ((size_t)(b * Hh + h) * Ts + t) * Dh + 2 * p;
    g_q[base]     = qe * c - qo * s;
    g_q[base + 1] = qe * s + qo * c;
    g_k[base]     = ke * c - ko * s;
    g_k[base + 1] = ke * s + ko * c;
    g_v[base]     = ve;
    g_v[base + 1] = vo;
}

// ---------------------------------------------------------------------------
// Flash attention with tf32 tensor cores.
// Block: 128 threads (4 warps) handles 64 query rows of one (b,h).
// Warp w owns rows [w*16, w*16+16). K/V tiles of 64 keys.
// tf32 conversion at smem store; mainloop LDS + MMA.
// ---------------------------------------------------------------------------
constexpr int FQ = 64, FK = 64;

__global__ __launch_bounds__(128) void flash_tf32_kernel(
    const int* __restrict__ amask)
{
    __shared__ uint32_t Qs[FQ][Dh + 4];   // reused as Ps after Q frags built
    __shared__ uint32_t Ks[FK][Dh + 4];
    __shared__ uint32_t Vs[FK][Dh + 4];
    __shared__ int      Ms[FK];

    const int tid = threadIdx.x;
    const int wid = tid >> 5;
    const int lane = tid & 31;
    const int lr = lane >> 2;
    const int lc = lane & 3;
    const int h = blockIdx.y;
    const int b = blockIdx.z;
    const int q0 = blockIdx.x * FQ;
    const int wq = wid * 16;

    const float* qg = g_q + ((size_t)(b * Hh + h) * Ts + q0) * Dh;
    const float* kg = g_k + ((size_t)(b * Hh + h) * Ts) * Dh;
    const float* vg = g_v + ((size_t)(b * Hh + h) * Ts) * Dh;

    // Load Q tile (pre-scaled by 1/sqrt(Dh)), convert to tf32.
    #pragma unroll
    for (int i = 0; i < 8; i++) {
        int e = i * 128 + tid;       // float4 idx 0..1023
        int r = e >> 4;
        int c = (e & 15) * 4;
        float4 v = *reinterpret_cast<const float4*>(&qg[(size_t)r * Dh + c]);
        Qs[r][c]     = f2tf32(v.x * 0.125f);
        Qs[r][c + 1] = f2tf32(v.y * 0.125f);
        Qs[r][c + 2] = f2tf32(v.z * 0.125f);
        Qs[r][c + 3] = f2tf32(v.w * 0.125f);
    }
    __syncthreads();

    // Build Q fragments: 8 k-frags over Dh=64.
    uint32_t qf[8][4];
    #pragma unroll
    for (int kf = 0; kf < 8; kf++) {
        int kb = kf * 8;
        qf[kf][0] = Qs[wq + lr][kb + lc];
        qf[kf][1] = Qs[wq + lr + 8][kb + lc];
        qf[kf][2] = Qs[wq + lr][kb + lc + 4];
        qf[kf][3] = Qs[wq + lr + 8][kb + lc + 4];
    }
    __syncthreads();   // Qs now reusable as Ps

    float oacc[8][4] = {};   // O accumulators: 8 n-frags over Dh
    float m0 = -1e30f, m1 = -1e30f, l0 = 0.0f, l1 = 0.0f;
    const int r0g = q0 + wq + lr;   // global query rows owned by this lane
    const int ntiles = blockIdx.x + 1;

    for (int t = 0; t < ntiles; t++) {
        const int k0 = t * FK;
        __syncthreads();   // protect Ks/Vs/Ps reuse from previous iter
        // Load K, V tiles + mask (convert to tf32 at store)
        #pragma unroll
        for (int i = 0; i < 8; i++) {
            int e = i * 128 + tid;
            int r = e >> 4;
            int c = (e & 15) * 4;
            float4 kv = *reinterpret_cast<const float4*>(&kg[(size_t)(k0 + r) * Dh + c]);
            float4 vv = *reinterpret_cast<const float4*>(&vg[(size_t)(k0 + r) * Dh + c]);
            Ks[r][c]     = f2tf32(kv.x);
            Ks[r][c + 1] = f2tf32(kv.y);
            Ks[r][c + 2] = f2tf32(kv.z);
            Ks[r][c + 3] = f2tf32(kv.w);
            Vs[r][c]     = f2tf32(vv.x);
            Vs[r][c + 1] = f2tf32(vv.y);
            Vs[r][c + 2] = f2tf32(vv.z);
            Vs[r][c + 3] = f2tf32(vv.w);
        }
        if (tid < FK) Ms[tid] = amask[b * Ts + k0 + tid];
        __syncthreads();

        // S = Qscaled @ K^T : sacc[nf][4], nf over 64 keys
        float sacc[8][4] = {};
        #pragma unroll
        for (int kf = 0; kf < 8; kf++) {
            int kb = kf * 8;
            #pragma unroll
            for (int nf = 0; nf < 8; nf++) {
                uint32_t bf[2];
                bf[0] = Ks[nf * 8 + lr][kb + lc];
                bf[1] = Ks[nf * 8 + lr][kb + lc + 4];
                mma_tf32(sacc[nf], qf[kf], bf);
            }
        }

        // Masking: pad mask always; causal only on diagonal tile.
        const bool diag = (t == ntiles - 1);
        #pragma unroll
        for (int nf = 0; nf < 8; nf++) {
            int cA = nf * 8 + 2 * lc;
            int cB = cA + 1;
            bool mA = Ms[cA], mB = Ms[cB];
            if (!mA) { sacc[nf][0] = -1e30f; sacc[nf][2] = -1e30f; }
            if (!mB) { sacc[nf][1] = -1e30f; sacc[nf][3] = -1e30f; }
            if (diag) {
                int gA = k0 + cA, gB = k0 + cB;
                if (gA > r0g)     sacc[nf][0] = -1e30f;
                if (gB > r0g)     sacc[nf][1] = -1e30f;
                if (gA > r0g + 8) sacc[nf][2] = -1e30f;
                if (gB > r0g + 8) sacc[nf][3] = -1e30f;
            }
        }

        // Row max across registers + the 4 lanes sharing each row.
        float mx0 = -1e30f, mx1 = -1e30f;
        #pragma unroll
        for (int nf = 0; nf < 8; nf++) {
            mx0 = fmaxf(mx0, fmaxf(sacc[nf][0], sacc[nf][1]));
            mx1 = fmaxf(mx1, fmaxf(sacc[nf][2], sacc[nf][3]));
        }
        mx0 = fmaxf(mx0, __shfl_xor_sync(0xffffffff, mx0, 1));
        mx0 = fmaxf(mx0, __shfl_xor_sync(0xffffffff, mx0, 2));
        mx1 = fmaxf(mx1, __shfl_xor_sync(0xffffffff, mx1, 1));
        mx1 = fmaxf(mx1, __shfl_xor_sync(0xffffffff, mx1, 2));

        float nm0 = fmaxf(m0, mx0), nm1 = fmaxf(m1, mx1);
        float cr0 = __expf(m0 - nm0), cr1 = __expf(m1 - nm1);

        // P = exp(S - m) -> Ps (rows owned by this warp), accumulate row sums.
        float rs0 = 0.0f, rs1 = 0.0f;
        #pragma unroll
        for (int nf = 0; nf < 8; nf++) {
            int cc = nf * 8 + 2 * lc;
            float p0 = __expf(sacc[nf][0] - nm0);
            float p1 = __expf(sacc[nf][1] - nm0);
            float p2 = __expf(sacc[nf][2] - nm1);
            float p3 = __expf(sacc[nf][3] - nm1);
            rs0 += p0 + p1;
            rs1 += p2 + p3;
            Qs[wq + lr][cc]         = f2tf32(p0);
            Qs[wq + lr][cc + 1]     = f2tf32(p1);
            Qs[wq + lr + 8][cc]     = f2tf32(p2);
            Qs[wq + lr + 8][cc + 1] = f2tf32(p3);
        }
        rs0 += __shfl_xor_sync(0xffffffff, rs0, 1);
        rs0 += __shfl_xor_sync(0xffffffff, rs0, 2);
        rs1 += __shfl_xor_sync(0xffffffff, rs1, 1);
        rs1 += __shfl_xor_sync(0xffffffff, rs1, 2);

        l0 = l0 * cr0 + rs0;
        l1 = l1 * cr1 + rs1;
        m0 = nm0; m1 = nm1;

        // Rescale O accumulators.
        #pragma unroll
        for (int nf = 0; nf < 8; nf++) {
            oacc[nf][0] *= cr0; oacc[nf][1] *= cr0;
            oacc[nf][2] *= cr1; oacc[nf][3] *= cr1;
        }
        __syncwarp();

        // O += P @ V.  A = Ps (this warp's 16 rows, k over 64 keys), B = Vs.
        #pragma unroll
        for (int kf = 0; kf < 8; kf++) {
            int kb = kf * 8;
            uint32_t pf[4];
            pf[0] = Qs[wq + lr][kb + lc];
            pf[1] = Qs[wq + lr + 8][kb + lc];
            pf[2] = Qs[wq + lr][kb + lc + 4];
            pf[3] = Qs[wq + lr + 8][kb + lc + 4];
            #pragma unroll
            for (int nf = 0; nf < 8; nf++) {
                uint32_t vf[2];
                vf[0] = Vs[kb + lc][nf * 8 + lr];
                vf[1] = Vs[kb + lc + 4][nf * 8 + lr];
                mma_tf32(oacc[nf], pf, vf);
            }
        }
    }

    // Epilogue: O /= l, scatter into [BT, Dm] layout.
    float inv0 = (l0 > 0.0f) ? (1.0f / l0) : 0.0f;
    float inv1 = (l1 > 0.0f) ? (1.0f / l1) : 0.0f;
    float* out0 = g_attn + (size_t)(b * Ts + r0g) * Dm + h * Dh;
    float* out1 = g_attn + (size_t)(b * Ts + r0g + 8) * Dm + h * Dh;
    #pragma unroll
    for (int nf = 0; nf < 8; nf++) {
        int cc = nf * 8 + 2 * lc;
        out0[cc]     = oacc[nf][0] * inv0;
        out0[cc + 1] = oacc[nf][1] * inv0;
        out1[cc]     = oacc[nf][2] * inv1;
        out1[cc + 1] = oacc[nf][3] * inv1;
    }
}

// ---------------------------------------------------------------------------
// Launch
// ---------------------------------------------------------------------------
extern "C" void kernel_launch(void* const* d_in, const int* in_sizes, int n_in,
                              void* d_out, int out_size)
{
    const float* x      = (const float*)d_in[0];
    const int*   amask  = (const int*)  d_in[1];
    const float* W_qkv  = (const float*)d_in[2];
    const float* b_qkv  = (const float*)d_in[3];
    const float* W_out  = (const float*)d_in[4];
    const float* b_out  = (const float*)d_in[5];
    float* out = (float*)d_out;

    float *p_qkv, *p_attn;
    cudaGetSymbolAddress((void**)&p_qkv,  g_qkv);
    cudaGetSymbolAddress((void**)&p_attn, g_attn);

    // 1) QKV GEMM: [4096,1024] @ [1024,3072] + bias
    {
        dim3 grid((3 * Dm) / GBN, BT / GBM);
        gemm_tf32_kernel<<<grid, 256>>>(x, W_qkv, b_qkv, p_qkv, BT, 3 * Dm, Dm);
    }
    // 2) RoPE + scatter to [b,h,t,d]
    {
        int total = Bb * Ts * Hh * (Dh / 2);
        rope_scatter_kernel<<<(total + 255) / 256, 256>>>();
    }
    // 3) Flash attention (tf32 tensor cores)
    {
        dim3 grid(Ts / FQ, Hh, Bb);
        flash_tf32_kernel<<<grid, 128>>>(amask);
    }
    // 4) Output projection: [4096,1024] @ [1024,1024] + bias -> d_out
    {
        dim3 grid(Dm / GBN, BT / GBM);
        gemm_tf32_kernel<<<grid, 256>>>(p_attn, W_out, b_out, out, BT, Dm, Dm);
    }
}

// round 4
// speedup vs baseline: 3.7671x; 1.2202x over previous
#include <cuda_runtime.h>
#include <math.h>
#include <stdint.h>

// Problem constants
constexpr int Bb = 2;
constexpr int Ts = 2048;
constexpr int Dm = 1024;
constexpr int Hh = 16;
constexpr int Dh = 64;
constexpr int BT = Bb * Ts;

// Scratch (device globals — no allocation allowed)
__device__ float g_qkv[BT * 3 * Dm];
__device__ float g_q[Bb * Hh * Ts * Dh];
__device__ float g_k[Bb * Hh * Ts * Dh];
__device__ float g_v[Bb * Hh * Ts * Dh];
__device__ float g_attn[BT * Dm];
__device__ float g_xt[BT * Dm];          // tf32-rounded x
__device__ float g_wq[Dm * 3 * Dm];      // tf32-rounded W_qkv
__device__ float g_wo[Dm * Dm];          // tf32-rounded W_out

// ---------------------------------------------------------------------------
// helpers
// ---------------------------------------------------------------------------
__device__ __forceinline__ uint32_t f2tf32(float f) {
    uint32_t r;
    asm("cvt.rna.tf32.f32 %0, %1;" : "=r"(r) : "f"(f));
    return r;
}
__device__ __forceinline__ float tf32f(float f) { return __uint_as_float(f2tf32(f)); }

__device__ __forceinline__ void mma_tf32(float* c, const uint32_t* a, const uint32_t* b) {
    asm volatile(
        "mma.sync.aligned.m16n8k8.row.col.f32.tf32.tf32.f32 "
        "{%0,%1,%2,%3},{%4,%5,%6,%7},{%8,%9},{%0,%1,%2,%3};"
        : "+f"(c[0]), "+f"(c[1]), "+f"(c[2]), "+f"(c[3])
        : "r"(a[0]), "r"(a[1]), "r"(a[2]), "r"(a[3]), "r"(b[0]), "r"(b[1]));
}

__device__ __forceinline__ void cp16(void* dst_smem, const void* src) {
    uint32_t d = (uint32_t)__cvta_generic_to_shared(dst_smem);
    asm volatile("cp.async.cg.shared.global [%0], [%1], 16;" :: "r"(d), "l"(src));
}
#define CP_COMMIT() asm volatile("cp.async.commit_group;")
#define CP_WAIT1()  asm volatile("cp.async.wait_group 1;")
#define CP_WAIT0()  asm volatile("cp.async.wait_group 0;")

// ---------------------------------------------------------------------------
// prep: tf32-round x, W_qkv, W_out (vectorized)
// ---------------------------------------------------------------------------
__global__ void prep_tf32_kernel(const float* __restrict__ x,
                                 const float* __restrict__ wq,
                                 const float* __restrict__ wo)
{
    const int n1 = BT * Dm / 4;
    const int n2 = 3 * Dm * Dm / 4;
    const int n3 = Dm * Dm / 4;
    int i = blockIdx.x * blockDim.x + threadIdx.x;
    if (i < n1) {
        float4 v = reinterpret_cast<const float4*>(x)[i];
        v.x = tf32f(v.x); v.y = tf32f(v.y); v.z = tf32f(v.z); v.w = tf32f(v.w);
        reinterpret_cast<float4*>(g_xt)[i] = v;
    } else if (i < n1 + n2) {
        int j = i - n1;
        float4 v = reinterpret_cast<const float4*>(wq)[j];
        v.x = tf32f(v.x); v.y = tf32f(v.y); v.z = tf32f(v.z); v.w = tf32f(v.w);
        reinterpret_cast<float4*>(g_wq)[j] = v;
    } else if (i < n1 + n2 + n3) {
        int j = i - n1 - n2;
        float4 v = reinterpret_cast<const float4*>(wo)[j];
        v.x = tf32f(v.x); v.y = tf32f(v.y); v.z = tf32f(v.z); v.w = tf32f(v.w);
        reinterpret_cast<float4*>(g_wo)[j] = v;
    }
}

// ---------------------------------------------------------------------------
// Pipelined TF32 GEMM: C = A @ B + bias. A,B already tf32-rounded.
// 128x128x32 tiles, 256 thr, 8 warps (warp tile 64x32), cp.async 2-stage.
// ---------------------------------------------------------------------------
constexpr int GBM = 128, GBN = 128, GBK = 32;
constexpr int APITCH = 36;    // bank-stride 4 -> (4*lr+lc) conflict-free
constexpr int BPITCH = 136;   // bank-stride 8 -> (8*lc+lr) conflict-free

__global__ __launch_bounds__(256, 2) void gemm_tf32_pipe(
    const float* __restrict__ A, const float* __restrict__ Bm,
    const float* __restrict__ bias, float* __restrict__ C,
    int M, int N, int K)
{
    __shared__ uint32_t As[2][GBM][APITCH];   // [m][k]
    __shared__ uint32_t Bs[2][GBK][BPITCH];   // [k][n]

    const int tid = threadIdx.x;
    const int wid = tid >> 5;
    const int lane = tid & 31;
    const int lr = lane >> 2;
    const int lc = lane & 3;
    const int wm = (wid >> 2) * 64;
    const int wn = (wid & 3) * 32;
    const int row0 = blockIdx.y * GBM;
    const int col0 = blockIdx.x * GBN;

    float acc[4][4][4] = {};

#define GEMM_LOAD(s, k0)                                                       \
    {                                                                          \
        _Pragma("unroll")                                                      \
        for (int i = 0; i < 4; i++) {                                          \
            int e = i * 256 + tid; int r = e >> 3; int c = (e & 7) * 4;        \
            cp16(&As[s][r][c], &A[(size_t)(row0 + r) * K + (k0) + c]);         \
        }                                                                      \
        _Pragma("unroll")                                                      \
        for (int i = 0; i < 4; i++) {                                          \
            int e = i * 256 + tid; int r = e >> 5; int c = (e & 31) * 4;       \
            cp16(&Bs[s][r][c], &Bm[(size_t)((k0) + r) * N + col0 + c]);        \
        }                                                                      \
    }

    const int nk = K / GBK;
    GEMM_LOAD(0, 0);
    CP_COMMIT();

    for (int ks = 0; ks < nk; ks++) {
        if (ks + 1 < nk) {
            GEMM_LOAD((ks + 1) & 1, (ks + 1) * GBK);
            CP_COMMIT();
            CP_WAIT1();
        } else {
            CP_WAIT0();
        }
        __syncthreads();

        const int s = ks & 1;
        #pragma unroll
        for (int kk = 0; kk < GBK; kk += 8) {
            uint32_t af[4][4];
            uint32_t bf[4][2];
            #pragma unroll
            for (int mf = 0; mf < 4; mf++) {
                int mb = wm + mf * 16;
                af[mf][0] = As[s][mb + lr][kk + lc];
                af[mf][1] = As[s][mb + lr + 8][kk + lc];
                af[mf][2] = As[s][mb + lr][kk + lc + 4];
                af[mf][3] = As[s][mb + lr + 8][kk + lc + 4];
            }
            #pragma unroll
            for (int nf = 0; nf < 4; nf++) {
                int nb = wn + nf * 8;
                bf[nf][0] = Bs[s][kk + lc][nb + lr];
                bf[nf][1] = Bs[s][kk + lc + 4][nb + lr];
            }
            #pragma unroll
            for (int mf = 0; mf < 4; mf++)
                #pragma unroll
                for (int nf = 0; nf < 4; nf++)
                    mma_tf32(acc[mf][nf], af[mf], bf[nf]);
        }
        __syncthreads();
    }
#undef GEMM_LOAD

    #pragma unroll
    for (int mf = 0; mf < 4; mf++) {
        int r = row0 + wm + mf * 16 + lr;
        #pragma unroll
        for (int nf = 0; nf < 4; nf++) {
            int c = col0 + wn + nf * 8 + 2 * lc;
            float2 v0 = { acc[mf][nf][0] + bias[c], acc[mf][nf][1] + bias[c + 1] };
            float2 v1 = { acc[mf][nf][2] + bias[c], acc[mf][nf][3] + bias[c + 1] };
            *reinterpret_cast<float2*>(&C[(size_t)r * N + c]) = v0;
            *reinterpret_cast<float2*>(&C[(size_t)(r + 8) * N + c]) = v1;
        }
    }
}

// ---------------------------------------------------------------------------
// RoPE + scatter. Q pre-scaled by (1/sqrt(Dh))*log2(e) for exp2-domain
// softmax; q/k/v written tf32-rounded.
// ---------------------------------------------------------------------------
__global__ void rope_scatter_kernel()
{
    const float QSCALE = 0.125f * 1.4426950408889634f;
    int idx = blockIdx.x * blockDim.x + threadIdx.x;
    const int NPAIR = Dh / 2;
    const int TOTAL = Bb * Ts * Hh * NPAIR;
    if (idx >= TOTAL) return;

    int p = idx % NPAIR;
    int h = (idx / NPAIR) % Hh;
    int t = (idx / (NPAIR * Hh)) % Ts;
    int b = idx / (NPAIR * Hh * Ts);

    const float* row = g_qkv + (size_t)(b * Ts + t) * (3 * Dm);
    int col = h * Dh + 2 * p;

    float e = -((float)(2 * p) / (float)Dh) * log2f(10000.0f);
    float inv_freq = exp2f(e);
    float ang = (float)t * inv_freq;
    float s, c;
    sincosf(ang, &s, &c);

    float qe = row[col],          qo = row[col + 1];
    float ke = row[Dm + col],     ko = row[Dm + col + 1];
    float ve = row[2 * Dm + col], vo = row[2 * Dm + col + 1];

    size_t base = ((size_t)(b * Hh + h) * Ts + t) * Dh + 2 * p;
    g_q[base]     = tf32f((qe * c - qo * s) * QSCALE);
    g_q[base + 1] = tf32f((qe * s + qo * c) * QSCALE);
    g_k[base]     = tf32f(ke * c - ko * s);
    g_k[base + 1] = tf32f(ke * s + ko * c);
    g_v[base]     = tf32f(ve);
    g_v[base + 1] = tf32f(vo);
}

// ---------------------------------------------------------------------------
// Flash attention, tf32 mma, 256 thr (8 warps), FQ=128 queries, FK=64 keys,
// cp.async double-buffered K/V/mask, exp2-domain softmax.
// ---------------------------------------------------------------------------
constexpr int FQ = 128, FK = 64, FP = 68;   // FP pitch: bank-stride 4

__global__ __launch_bounds__(256, 2) void flash_tf32_kernel(
    const int* __restrict__ amask)
{
    __shared__ uint32_t Ps[FQ][FP];        // Q at start, then P
    __shared__ uint32_t Ksm[2][FK][FP];
    __shared__ uint32_t Vsm[2][FK][FP];
    __shared__ int      Msm[2][FK];

    const int tid = threadIdx.x;
    const int wid = tid >> 5;
    const int lane = tid & 31;
    const int lr = lane >> 2;
    const int lc = lane & 3;
    const int h = blockIdx.y;
    const int b = blockIdx.z;
    const int qb = gridDim.x - 1 - blockIdx.x;   // big blocks first
    const int q0 = qb * FQ;
    const int wq = wid * 16;

    const float* qg = g_q + ((size_t)(b * Hh + h) * Ts + q0) * Dh;
    const float* kg = g_k + ((size_t)(b * Hh + h) * Ts) * Dh;
    const float* vg = g_v + ((size_t)(b * Hh + h) * Ts) * Dh;
    const int*   mk = amask + b * Ts;

    const int nt = 2 * qb + 2;   // number of 64-key tiles

#define FLASH_LOAD(s, k0)                                                      \
    {                                                                          \
        _Pragma("unroll")                                                      \
        for (int i = 0; i < 4; i++) {                                          \
            int e = i * 256 + tid; int r = e >> 4; int c = (e & 15) * 4;       \
            cp16(&Ksm[s][r][c], kg + (size_t)((k0) + r) * Dh + c);             \
            cp16(&Vsm[s][r][c], vg + (size_t)((k0) + r) * Dh + c);             \
        }                                                                      \
        if (tid < 16) cp16(&Msm[s][tid * 4], mk + (k0) + tid * 4);             \
    }

    // issue tile 0, then load Q while it flies
    FLASH_LOAD(0, 0);
    CP_COMMIT();

    #pragma unroll
    for (int i = 0; i < 8; i++) {
        int e = i * 256 + tid;
        int r = e >> 4;
        int c = (e & 15) * 4;
        *reinterpret_cast<uint4*>(&Ps[r][c]) =
            *reinterpret_cast<const uint4*>(&qg[(size_t)r * Dh + c]);
    }
    __syncthreads();

    uint32_t qf[8][4];
    #pragma unroll
    for (int kf = 0; kf < 8; kf++) {
        int kb = kf * 8;
        qf[kf][0] = Ps[wq + lr][kb + lc];
        qf[kf][1] = Ps[wq + lr + 8][kb + lc];
        qf[kf][2] = Ps[wq + lr][kb + lc + 4];
        qf[kf][3] = Ps[wq + lr + 8][kb + lc + 4];
    }
    __syncthreads();   // Ps now reusable as P

    float oacc[8][4] = {};
    float m0 = -1e30f, m1 = -1e30f, l0 = 0.0f, l1 = 0.0f;
    const int r0g = q0 + wq + lr;

    for (int t = 0; t < nt; t++) {
        const int k0 = t * FK;
        if (t + 1 < nt) {
            FLASH_LOAD((t + 1) & 1, (t + 1) * FK);
            CP_COMMIT();
            CP_WAIT1();
        } else {
            CP_WAIT0();
        }
        __syncthreads();
        const int st = t & 1;

        // S = Q @ K^T (log2-domain logits)
        float sacc[8][4] = {};
        #pragma unroll
        for (int kf = 0; kf < 8; kf++) {
            int kb = kf * 8;
            #pragma unroll
            for (int nf = 0; nf < 8; nf++) {
                uint32_t bfr[2];
                bfr[0] = Ksm[st][nf * 8 + lr][kb + lc];
                bfr[1] = Ksm[st][nf * 8 + lr][kb + lc + 4];
                mma_tf32(sacc[nf], qf[kf], bfr);
            }
        }

        // Masking
        const bool diag = (k0 + FK - 1 > q0);
        #pragma unroll
        for (int nf = 0; nf < 8; nf++) {
            int cA = nf * 8 + 2 * lc;
            int cB = cA + 1;
            if (!Msm[st][cA]) { sacc[nf][0] = -1e30f; sacc[nf][2] = -1e30f; }
            if (!Msm[st][cB]) { sacc[nf][1] = -1e30f; sacc[nf][3] = -1e30f; }
            if (diag) {
                int gA = k0 + cA, gB = k0 + cB;
                if (gA > r0g)     sacc[nf][0] = -1e30f;
                if (gB > r0g)     sacc[nf][1] = -1e30f;
                if (gA > r0g + 8) sacc[nf][2] = -1e30f;
                if (gB > r0g + 8) sacc[nf][3] = -1e30f;
            }
        }

        // Row max (regs + 4-lane groups)
        float mx0 = -1e30f, mx1 = -1e30f;
        #pragma unroll
        for (int nf = 0; nf < 8; nf++) {
            mx0 = fmaxf(mx0, fmaxf(sacc[nf][0], sacc[nf][1]));
            mx1 = fmaxf(mx1, fmaxf(sacc[nf][2], sacc[nf][3]));
        }
        mx0 = fmaxf(mx0, __shfl_xor_sync(0xffffffff, mx0, 1));
        mx0 = fmaxf(mx0, __shfl_xor_sync(0xffffffff, mx0, 2));
        mx1 = fmaxf(mx1, __shfl_xor_sync(0xffffffff, mx1, 1));
        mx1 = fmaxf(mx1, __shfl_xor_sync(0xffffffff, mx1, 2));

        float nm0 = fmaxf(m0, mx0), nm1 = fmaxf(m1, mx1);
        float cr0 = exp2f(m0 - nm0), cr1 = exp2f(m1 - nm1);

        // P = exp2(S - m), row sums, store tf32 P
        float rs0 = 0.0f, rs1 = 0.0f;
        #pragma unroll
        for (int nf = 0; nf < 8; nf++) {
            int cc = nf * 8 + 2 * lc;
            float p0 = exp2f(sacc[nf][0] - nm0);
            float p1 = exp2f(sacc[nf][1] - nm0);
            float p2 = exp2f(sacc[nf][2] - nm1);
            float p3 = exp2f(sacc[nf][3] - nm1);
            rs0 += p0 + p1;
            rs1 += p2 + p3;
            uint2 a = { f2tf32(p0), f2tf32(p1) };
            uint2 bq = { f2tf32(p2), f2tf32(p3) };
            *reinterpret_cast<uint2*>(&Ps[wq + lr][cc]) = a;
            *reinterpret_cast<uint2*>(&Ps[wq + lr + 8][cc]) = bq;
        }
        rs0 += __shfl_xor_sync(0xffffffff, rs0, 1);
        rs0 += __shfl_xor_sync(0xffffffff, rs0, 2);
        rs1 += __shfl_xor_sync(0xffffffff, rs1, 1);
        rs1 += __shfl_xor_sync(0xffffffff, rs1, 2);

        l0 = l0 * cr0 + rs0;
        l1 = l1 * cr1 + rs1;
        m0 = nm0; m1 = nm1;

        #pragma unroll
        for (int nf = 0; nf < 8; nf++) {
            oacc[nf][0] *= cr0; oacc[nf][1] *= cr0;
            oacc[nf][2] *= cr1; oacc[nf][3] *= cr1;
        }
        __syncwarp();

        // O += P @ V
        #pragma unroll
        for (int kf = 0; kf < 8; kf++) {
            int kb = kf * 8;
            uint32_t pf[4];
            pf[0] = Ps[wq + lr][kb + lc];
            pf[1] = Ps[wq + lr + 8][kb + lc];
            pf[2] = Ps[wq + lr][kb + lc + 4];
            pf[3] = Ps[wq + lr + 8][kb + lc + 4];
            #pragma unroll
            for (int nf = 0; nf < 8; nf++) {
                uint32_t vf[2];
                vf[0] = Vsm[st][kb + lc][nf * 8 + lr];
                vf[1] = Vsm[st][kb + lc + 4][nf * 8 + lr];
                mma_tf32(oacc[nf], pf, vf);
            }
        }
        __syncthreads();
    }
#undef FLASH_LOAD

    // Epilogue: O /= l, write tf32-rounded into [BT, Dm]
    float inv0 = (l0 > 0.0f) ? (1.0f / l0) : 0.0f;
    float inv1 = (l1 > 0.0f) ? (1.0f / l1) : 0.0f;
    float* out0 = g_attn + (size_t)(b * Ts + r0g) * Dm + h * Dh;
    float* out1 = g_attn + (size_t)(b * Ts + r0g + 8) * Dm + h * Dh;
    #pragma unroll
    for (int nf = 0; nf < 8; nf++) {
        int cc = nf * 8 + 2 * lc;
        float2 v0 = { tf32f(oacc[nf][0] * inv0), tf32f(oacc[nf][1] * inv0) };
        float2 v1 = { tf32f(oacc[nf][2] * inv1), tf32f(oacc[nf][3] * inv1) };
        *reinterpret_cast<float2*>(&out0[cc]) = v0;
        *reinterpret_cast<float2*>(&out1[cc]) = v1;
    }
}

// ---------------------------------------------------------------------------
// Launch
// ---------------------------------------------------------------------------
extern "C" void kernel_launch(void* const* d_in, const int* in_sizes, int n_in,
                              void* d_out, int out_size)
{
    const float* x      = (const float*)d_in[0];
    const int*   amask  = (const int*)  d_in[1];
    const float* W_qkv  = (const float*)d_in[2];
    const float* b_qkv  = (const float*)d_in[3];
    const float* W_out  = (const float*)d_in[4];
    const float* b_out  = (const float*)d_in[5];
    float* out = (float*)d_out;

    float *p_qkv, *p_attn, *p_xt, *p_wq, *p_wo;
    cudaGetSymbolAddress((void**)&p_qkv,  g_qkv);
    cudaGetSymbolAddress((void**)&p_attn, g_attn);
    cudaGetSymbolAddress((void**)&p_xt,   g_xt);
    cudaGetSymbolAddress((void**)&p_wq,   g_wq);
    cudaGetSymbolAddress((void**)&p_wo,   g_wo);

    // 0) tf32-round inputs
    {
        int total = (BT * Dm + 3 * Dm * Dm + Dm * Dm) / 4;
        prep_tf32_kernel<<<(total + 255) / 256, 256>>>(x, W_qkv, W_out);
    }
    // 1) QKV GEMM
    {
        dim3 grid((3 * Dm) / GBN, BT / GBM);
        gemm_tf32_pipe<<<grid, 256>>>(p_xt, p_wq, b_qkv, p_qkv, BT, 3 * Dm, Dm);
    }
    // 2) RoPE + scatter (tf32-rounded, Q pre-scaled)
    {
        int total = Bb * Ts * Hh * (Dh / 2);
        rope_scatter_kernel<<<(total + 255) / 256, 256>>>();
    }
    // 3) Flash attention
    {
        dim3 grid(Ts / FQ, Hh, Bb);
        flash_tf32_kernel<<<grid, 256>>>(amask);
    }
    // 4) Output projection
    {
        dim3 grid(Dm / GBN, BT / GBM);
        gemm_tf32_pipe<<<grid, 256>>>(p_attn, p_wo, b_out, out, BT, Dm, Dm);
    }
}

// round 12
// speedup vs baseline: 4.4840x; 1.1903x over previous
#include <cuda_runtime.h>
#include <math.h>
#include <stdint.h>

// Problem constants
constexpr int Bb = 2;
constexpr int Ts = 2048;
constexpr int Dm = 1024;
constexpr int Hh = 16;
constexpr int Dh = 64;
constexpr int BT = Bb * Ts;

// Scratch (device globals — no allocation allowed)
__device__ float g_qkv[BT * 3 * Dm];
__device__ float g_q[Bb * Hh * Ts * Dh];
__device__ float g_k[Bb * Hh * Ts * Dh];
__device__ float g_v[Bb * Hh * Ts * Dh];
__device__ float g_attn[BT * Dm];
__device__ float g_xt[BT * Dm];          // tf32-rounded x
__device__ float g_wq[Dm * 3 * Dm];      // tf32-rounded W_qkv
__device__ float g_wo[Dm * Dm];          // tf32-rounded W_out

// ---------------------------------------------------------------------------
// helpers
// ---------------------------------------------------------------------------
__device__ __forceinline__ uint32_t f2tf32(float f) {
    uint32_t r;
    asm("cvt.rna.tf32.f32 %0, %1;" : "=r"(r) : "f"(f));
    return r;
}
__device__ __forceinline__ float tf32f(float f) { return __uint_as_float(f2tf32(f)); }

__device__ __forceinline__ void mma_tf32(float* c, const uint32_t* a, const uint32_t* b) {
    asm volatile(
        "mma.sync.aligned.m16n8k8.row.col.f32.tf32.tf32.f32 "
        "{%0,%1,%2,%3},{%4,%5,%6,%7},{%8,%9},{%0,%1,%2,%3};"
        : "+f"(c[0]), "+f"(c[1]), "+f"(c[2]), "+f"(c[3])
        : "r"(a[0]), "r"(a[1]), "r"(a[2]), "r"(a[3]), "r"(b[0]), "r"(b[1]));
}

__device__ __forceinline__ void cp16(void* dst_smem, const void* src) {
    uint32_t d = (uint32_t)__cvta_generic_to_shared(dst_smem);
    asm volatile("cp.async.cg.shared.global [%0], [%1], 16;" :: "r"(d), "l"(src));
}
#define CP_COMMIT() asm volatile("cp.async.commit_group;")
#define CP_WAIT1()  asm volatile("cp.async.wait_group 1;")
#define CP_WAIT0()  asm volatile("cp.async.wait_group 0;")

// ---------------------------------------------------------------------------
// prep: tf32-round x, W_qkv, W_out (vectorized)
// ---------------------------------------------------------------------------
__global__ void prep_tf32_kernel(const float* __restrict__ x,
                                 const float* __restrict__ wq,
                                 const float* __restrict__ wo)
{
    const int n1 = BT * Dm / 4;
    const int n2 = 3 * Dm * Dm / 4;
    const int n3 = Dm * Dm / 4;
    int i = blockIdx.x * blockDim.x + threadIdx.x;
    if (i < n1) {
        float4 v = reinterpret_cast<const float4*>(x)[i];
        v.x = tf32f(v.x); v.y = tf32f(v.y); v.z = tf32f(v.z); v.w = tf32f(v.w);
        reinterpret_cast<float4*>(g_xt)[i] = v;
    } else if (i < n1 + n2) {
        int j = i - n1;
        float4 v = reinterpret_cast<const float4*>(wq)[j];
        v.x = tf32f(v.x); v.y = tf32f(v.y); v.z = tf32f(v.z); v.w = tf32f(v.w);
        reinterpret_cast<float4*>(g_wq)[j] = v;
    } else if (i < n1 + n2 + n3) {
        int j = i - n1 - n2;
        float4 v = reinterpret_cast<const float4*>(wo)[j];
        v.x = tf32f(v.x); v.y = tf32f(v.y); v.z = tf32f(v.z); v.w = tf32f(v.w);
        reinterpret_cast<float4*>(g_wo)[j] = v;
    }
}

// ---------------------------------------------------------------------------
// Pipelined TF32 GEMM: C = A @ B + bias. A,B already tf32-rounded.
// 128x128x32 tiles, 256 thr, 8 warps (warp tile 64x32), cp.async 2-stage.
// ---------------------------------------------------------------------------
constexpr int GBM = 128, GBN = 128, GBK = 32;
constexpr int APITCH = 36;    // bank-stride 4 -> (4*lr+lc) conflict-free
constexpr int BPITCH = 136;   // bank-stride 8 -> (8*lc+lr) conflict-free

__global__ __launch_bounds__(256, 2) void gemm_tf32_pipe(
    const float* __restrict__ A, const float* __restrict__ Bm,
    const float* __restrict__ bias, float* __restrict__ C,
    int M, int N, int K)
{
    __shared__ uint32_t As[2][GBM][APITCH];   // [m][k]
    __shared__ uint32_t Bs[2][GBK][BPITCH];   // [k][n]

    const int tid = threadIdx.x;
    const int wid = tid >> 5;
    const int lane = tid & 31;
    const int lr = lane >> 2;
    const int lc = lane & 3;
    const int wm = (wid >> 2) * 64;
    const int wn = (wid & 3) * 32;
    const int row0 = blockIdx.y * GBM;
    const int col0 = blockIdx.x * GBN;

    float acc[4][4][4] = {};

#define GEMM_LOAD(s, k0)                                                       \
    {                                                                          \
        _Pragma("unroll")                                                      \
        for (int i = 0; i < 4; i++) {                                          \
            int e = i * 256 + tid; int r = e >> 3; int c = (e & 7) * 4;        \
            cp16(&As[s][r][c], &A[(size_t)(row0 + r) * K + (k0) + c]);         \
        }                                                                      \
        _Pragma("unroll")                                                      \
        for (int i = 0; i < 4; i++) {                                          \
            int e = i * 256 + tid; int r = e >> 5; int c = (e & 31) * 4;       \
            cp16(&Bs[s][r][c], &Bm[(size_t)((k0) + r) * N + col0 + c]);        \
        }                                                                      \
    }

    const int nk = K / GBK;
    GEMM_LOAD(0, 0);
    CP_COMMIT();

    for (int ks = 0; ks < nk; ks++) {
        if (ks + 1 < nk) {
            GEMM_LOAD((ks + 1) & 1, (ks + 1) * GBK);
            CP_COMMIT();
            CP_WAIT1();
        } else {
            CP_WAIT0();
        }
        __syncthreads();

        const int s = ks & 1;
        #pragma unroll
        for (int kk = 0; kk < GBK; kk += 8) {
            uint32_t af[4][4];
            uint32_t bf[4][2];
            #pragma unroll
            for (int mf = 0; mf < 4; mf++) {
                int mb = wm + mf * 16;
                af[mf][0] = As[s][mb + lr][kk + lc];
                af[mf][1] = As[s][mb + lr + 8][kk + lc];
                af[mf][2] = As[s][mb + lr][kk + lc + 4];
                af[mf][3] = As[s][mb + lr + 8][kk + lc + 4];
            }
            #pragma unroll
            for (int nf = 0; nf < 4; nf++) {
                int nb = wn + nf * 8;
                bf[nf][0] = Bs[s][kk + lc][nb + lr];
                bf[nf][1] = Bs[s][kk + lc + 4][nb + lr];
            }
            #pragma unroll
            for (int mf = 0; mf < 4; mf++)
                #pragma unroll
                for (int nf = 0; nf < 4; nf++)
                    mma_tf32(acc[mf][nf], af[mf], bf[nf]);
        }
        __syncthreads();
    }
#undef GEMM_LOAD

    #pragma unroll
    for (int mf = 0; mf < 4; mf++) {
        int r = row0 + wm + mf * 16 + lr;
        #pragma unroll
        for (int nf = 0; nf < 4; nf++) {
            int c = col0 + wn + nf * 8 + 2 * lc;
            float2 v0 = { acc[mf][nf][0] + bias[c], acc[mf][nf][1] + bias[c + 1] };
            float2 v1 = { acc[mf][nf][2] + bias[c], acc[mf][nf][3] + bias[c + 1] };
            *reinterpret_cast<float2*>(&C[(size_t)r * N + c]) = v0;
            *reinterpret_cast<float2*>(&C[(size_t)(r + 8) * N + c]) = v1;
        }
    }
}

// ---------------------------------------------------------------------------
// RoPE + scatter. Q pre-scaled by (1/sqrt(Dh))*log2(e) for exp2-domain
// softmax; q/k/v written tf32-rounded.
// ---------------------------------------------------------------------------
__global__ void rope_scatter_kernel()
{
    const float QSCALE = 0.125f * 1.4426950408889634f;
    int idx = blockIdx.x * blockDim.x + threadIdx.x;
    const int NPAIR = Dh / 2;
    const int TOTAL = Bb * Ts * Hh * NPAIR;
    if (idx >= TOTAL) return;

    int p = idx % NPAIR;
    int h = (idx / NPAIR) % Hh;
    int t = (idx / (NPAIR * Hh)) % Ts;
    int b = idx / (NPAIR * Hh * Ts);

    const float* row = g_qkv + (size_t)(b * Ts + t) * (3 * Dm);
    int col = h * Dh + 2 * p;

    float e = -((float)(2 * p) / (float)Dh) * log2f(10000.0f);
    float inv_freq = exp2f(e);
    float ang = (float)t * inv_freq;
    float s, c;
    sincosf(ang, &s, &c);

    float qe = row[col],          qo = row[col + 1];
    float ke = row[Dm + col],     ko = row[Dm + col + 1];
    float ve = row[2 * Dm + col], vo = row[2 * Dm + col + 1];

    size_t base = ((size_t)(b * Hh + h) * Ts + t) * Dh + 2 * p;
    g_q[base]     = tf32f((qe * c - qo * s) * QSCALE);
    g_q[base + 1] = tf32f((qe * s + qo * c) * QSCALE);
    g_k[base]     = tf32f(ke * c - ko * s);
    g_k[base + 1] = tf32f(ke * s + ko * c);
    g_v[base]     = tf32f(ve);
    g_v[base + 1] = tf32f(vo);
}

// ---------------------------------------------------------------------------
// Flash attention, tf32 mma, 256 thr (8 warps), FQ=128 queries, FK=64 keys,
// cp.async double-buffered K/V/mask, exp2-domain softmax.
// Grid: (Hh, Bb, Ts/FQ) with qb = gridDim.z-1-blockIdx.z so the heaviest
// (most-tiles) blocks launch first -> LPT wave packing, shorter tail.
// ---------------------------------------------------------------------------
constexpr int FQ = 128, FK = 64, FP = 68;   // FP pitch: bank-stride 4

__global__ __launch_bounds__(256, 2) void flash_tf32_kernel(
    const int* __restrict__ amask)
{
    __shared__ uint32_t Ps[FQ][FP];        // Q at start, then P
    __shared__ uint32_t Ksm[2][FK][FP];
    __shared__ uint32_t Vsm[2][FK][FP];
    __shared__ int      Msm[2][FK];

    const int tid = threadIdx.x;
    const int wid = tid >> 5;
    const int lane = tid & 31;
    const int lr = lane >> 2;
    const int lc = lane & 3;
    const int h = blockIdx.x;
    const int b = blockIdx.y;
    const int qb = gridDim.z - 1 - blockIdx.z;   // big blocks first
    const int q0 = qb * FQ;
    const int wq = wid * 16;

    const float* qg = g_q + ((size_t)(b * Hh + h) * Ts + q0) * Dh;
    const float* kg = g_k + ((size_t)(b * Hh + h) * Ts) * Dh;
    const float* vg = g_v + ((size_t)(b * Hh + h) * Ts) * Dh;
    const int*   mk = amask + b * Ts;

    const int nt = 2 * qb + 2;   // number of 64-key tiles

#define FLASH_LOAD(s, k0)                                                      \
    {                                                                          \
        _Pragma("unroll")                                                      \
        for (int i = 0; i < 4; i++) {                                          \
            int e = i * 256 + tid; int r = e >> 4; int c = (e & 15) * 4;       \
            cp16(&Ksm[s][r][c], kg + (size_t)((k0) + r) * Dh + c);             \
            cp16(&Vsm[s][r][c], vg + (size_t)((k0) + r) * Dh + c);             \
        }                                                                      \
        if (tid < 16) cp16(&Msm[s][tid * 4], mk + (k0) + tid * 4);             \
    }

    // issue tile 0, then load Q while it flies
    FLASH_LOAD(0, 0);
    CP_COMMIT();

    #pragma unroll
    for (int i = 0; i < 8; i++) {
        int e = i * 256 + tid;
        int r = e >> 4;
        int c = (e & 15) * 4;
        *reinterpret_cast<uint4*>(&Ps[r][c]) =
            *reinterpret_cast<const uint4*>(&qg[(size_t)r * Dh + c]);
    }
    __syncthreads();

    uint32_t qf[8][4];
    #pragma unroll
    for (int kf = 0; kf < 8; kf++) {
        int kb = kf * 8;
        qf[kf][0] = Ps[wq + lr][kb + lc];
        qf[kf][1] = Ps[wq + lr + 8][kb + lc];
        qf[kf][2] = Ps[wq + lr][kb + lc + 4];
        qf[kf][3] = Ps[wq + lr + 8][kb + lc + 4];
    }
    __syncthreads();   // Ps now reusable as P

    float oacc[8][4] = {};
    float m0 = -1e30f, m1 = -1e30f, l0 = 0.0f, l1 = 0.0f;
    const int r0g = q0 + wq + lr;

    for (int t = 0; t < nt; t++) {
        const int k0 = t * FK;
        if (t + 1 < nt) {
            FLASH_LOAD((t + 1) & 1, (t + 1) * FK);
            CP_COMMIT();
            CP_WAIT1();
        } else {
            CP_WAIT0();
        }
        __syncthreads();
        const int st = t & 1;

        // S = Q @ K^T (log2-domain logits)
        float sacc[8][4] = {};
        #pragma unroll
        for (int kf = 0; kf < 8; kf++) {
            int kb = kf * 8;
            #pragma unroll
            for (int nf = 0; nf < 8; nf++) {
                uint32_t bfr[2];
                bfr[0] = Ksm[st][nf * 8 + lr][kb + lc];
                bfr[1] = Ksm[st][nf * 8 + lr][kb + lc + 4];
                mma_tf32(sacc[nf], qf[kf], bfr);
            }
        }

        // Masking
        const bool diag = (k0 + FK - 1 > q0);
        #pragma unroll
        for (int nf = 0; nf < 8; nf++) {
            int cA = nf * 8 + 2 * lc;
            int cB = cA + 1;
            if (!Msm[st][cA]) { sacc[nf][0] = -1e30f; sacc[nf][2] = -1e30f; }
            if (!Msm[st][cB]) { sacc[nf][1] = -1e30f; sacc[nf][3] = -1e30f; }
            if (diag) {
                int gA = k0 + cA, gB = k0 + cB;
                if (gA > r0g)     sacc[nf][0] = -1e30f;
                if (gB > r0g)     sacc[nf][1] = -1e30f;
                if (gA > r0g + 8) sacc[nf][2] = -1e30f;
                if (gB > r0g + 8) sacc[nf][3] = -1e30f;
            }
        }

        // Row max (regs + 4-lane groups)
        float mx0 = -1e30f, mx1 = -1e30f;
        #pragma unroll
        for (int nf = 0; nf < 8; nf++) {
            mx0 = fmaxf(mx0, fmaxf(sacc[nf][0], sacc[nf][1]));
            mx1 = fmaxf(mx1, fmaxf(sacc[nf][2], sacc[nf][3]));
        }
        mx0 = fmaxf(mx0, __shfl_xor_sync(0xffffffff, mx0, 1));
        mx0 = fmaxf(mx0, __shfl_xor_sync(0xffffffff, mx0, 2));
        mx1 = fmaxf(mx1, __shfl_xor_sync(0xffffffff, mx1, 1));
        mx1 = fmaxf(mx1, __shfl_xor_sync(0xffffffff, mx1, 2));

        float nm0 = fmaxf(m0, mx0), nm1 = fmaxf(m1, mx1);
        float cr0 = exp2f(m0 - nm0), cr1 = exp2f(m1 - nm1);

        // P = exp2(S - m), row sums, store tf32 P
        float rs0 = 0.0f, rs1 = 0.0f;
        #pragma unroll
        for (int nf = 0; nf < 8; nf++) {
            int cc = nf * 8 + 2 * lc;
            float p0 = exp2f(sacc[nf][0] - nm0);
            float p1 = exp2f(sacc[nf][1] - nm0);
            float p2 = exp2f(sacc[nf][2] - nm1);
            float p3 = exp2f(sacc[nf][3] - nm1);
            rs0 += p0 + p1;
            rs1 += p2 + p3;
            uint2 a = { f2tf32(p0), f2tf32(p1) };
            uint2 bq = { f2tf32(p2), f2tf32(p3) };
            *reinterpret_cast<uint2*>(&Ps[wq + lr][cc]) = a;
            *reinterpret_cast<uint2*>(&Ps[wq + lr + 8][cc]) = bq;
        }
        rs0 += __shfl_xor_sync(0xffffffff, rs0, 1);
        rs0 += __shfl_xor_sync(0xffffffff, rs0, 2);
        rs1 += __shfl_xor_sync(0xffffffff, rs1, 1);
        rs1 += __shfl_xor_sync(0xffffffff, rs1, 2);

        l0 = l0 * cr0 + rs0;
        l1 = l1 * cr1 + rs1;
        m0 = nm0; m1 = nm1;

        #pragma unroll
        for (int nf = 0; nf < 8; nf++) {
            oacc[nf][0] *= cr0; oacc[nf][1] *= cr0;
            oacc[nf][2] *= cr1; oacc[nf][3] *= cr1;
        }
        __syncwarp();

        // O += P @ V
        #pragma unroll
        for (int kf = 0; kf < 8; kf++) {
            int kb = kf * 8;
            uint32_t pf[4];
            pf[0] = Ps[wq + lr][kb + lc];
            pf[1] = Ps[wq + lr + 8][kb + lc];
            pf[2] = Ps[wq + lr][kb + lc + 4];
            pf[3] = Ps[wq + lr + 8][kb + lc + 4];
            #pragma unroll
            for (int nf = 0; nf < 8; nf++) {
                uint32_t vf[2];
                vf[0] = Vsm[st][kb + lc][nf * 8 + lr];
                vf[1] = Vsm[st][kb + lc + 4][nf * 8 + lr];
                mma_tf32(oacc[nf], pf, vf);
            }
        }
        __syncthreads();
    }
#undef FLASH_LOAD

    // Epilogue: O /= l, write tf32-rounded into [BT, Dm]
    float inv0 = (l0 > 0.0f) ? (1.0f / l0) : 0.0f;
    float inv1 = (l1 > 0.0f) ? (1.0f / l1) : 0.0f;
    float* out0 = g_attn + (size_t)(b * Ts + r0g) * Dm + h * Dh;
    float* out1 = g_attn + (size_t)(b * Ts + r0g + 8) * Dm + h * Dh;
    #pragma unroll
    for (int nf = 0; nf < 8; nf++) {
        int cc = nf * 8 + 2 * lc;
        float2 v0 = { tf32f(oacc[nf][0] * inv0), tf32f(oacc[nf][1] * inv0) };
        float2 v1 = { tf32f(oacc[nf][2] * inv1), tf32f(oacc[nf][3] * inv1) };
        *reinterpret_cast<float2*>(&out0[cc]) = v0;
        *reinterpret_cast<float2*>(&out1[cc]) = v1;
    }
}

// ---------------------------------------------------------------------------
// Launch
// ---------------------------------------------------------------------------
extern "C" void kernel_launch(void* const* d_in, const int* in_sizes, int n_in,
                              void* d_out, int out_size)
{
    const float* x      = (const float*)d_in[0];
    const int*   amask  = (const int*)  d_in[1];
    const float* W_qkv  = (const float*)d_in[2];
    const float* b_qkv  = (const float*)d_in[3];
    const float* W_out  = (const float*)d_in[4];
    const float* b_out  = (const float*)d_in[5];
    float* out = (float*)d_out;

    float *p_qkv, *p_attn, *p_xt, *p_wq, *p_wo;
    cudaGetSymbolAddress((void**)&p_qkv,  g_qkv);
    cudaGetSymbolAddress((void**)&p_attn, g_attn);
    cudaGetSymbolAddress((void**)&p_xt,   g_xt);
    cudaGetSymbolAddress((void**)&p_wq,   g_wq);
    cudaGetSymbolAddress((void**)&p_wo,   g_wo);

    // 0) tf32-round inputs
    {
        int total = (BT * Dm + 3 * Dm * Dm + Dm * Dm) / 4;
        prep_tf32_kernel<<<(total + 255) / 256, 256>>>(x, W_qkv, W_out);
    }
    // 1) QKV GEMM
    {
        dim3 grid((3 * Dm) / GBN, BT / GBM);
        gemm_tf32_pipe<<<grid, 256>>>(p_xt, p_wq, b_qkv, p_qkv, BT, 3 * Dm, Dm);
    }
    // 2) RoPE + scatter (tf32-rounded, Q pre-scaled)
    {
        int total = Bb * Ts * Hh * (Dh / 2);
        rope_scatter_kernel<<<(total + 255) / 256, 256>>>();
    }
    // 3) Flash attention (LPT: biggest query blocks launch first via gridDim.z)
    {
        dim3 grid(Hh, Bb, Ts / FQ);
        flash_tf32_kernel<<<grid, 256>>>(amask);
    }
    // 4) Output projection
    {
        dim3 grid(Dm / GBN, BT / GBM);
        gemm_tf32_pipe<<<grid, 256>>>(p_attn, p_wo, b_out, out, BT, Dm, Dm);
    }
}